// round 3
// baseline (speedup 1.0000x reference)
#include <cuda_runtime.h>
#include <math.h>

#define NB     4
#define NQ     1024
#define DIM    256
#define NHEADS 8
#define NPTS   4
#define GH     200
#define GW     200
#define NHW    (GH*GW)       // 40000
#define NROWS  (NB*NQ)       // 4096
#define NAUG   384           // 256 query | 64 off | 32 attn | 32 pad

// Scratch (__device__ globals: allocation-free per harness rules)
__device__ float g_qoa  [NROWS * NAUG];            // query | offsets | logits
__device__ float g_Waug [DIM * NAUG];
__device__ float g_baug [NAUG];
__device__ float g_attn [NROWS * 32];
__device__ int   g_cidx [NROWS * 128];             // [row][h][p][corner]
__device__ float g_cw   [NROWS * 128];
__device__ float g_bevT [(size_t)NB * NHW * DIM];  // [B, HW, C]
__device__ float g_samp [NROWS * DIM];
__device__ float g_msda [NROWS * DIM];

// ---------------------------------------------------------------------------
// Build augmented weights: W_aug = [ W_q | W_q@W_off | W_q@W_attn | 0 ]
// ---------------------------------------------------------------------------
__global__ __launch_bounds__(256)
void prep_weights(const float* __restrict__ W_q, const float* __restrict__ W_off,
                  const float* __restrict__ W_attn, float* __restrict__ W_aug)
{
    const int id = blockIdx.x * 256 + threadIdx.x;   // 256*384
    const int k = id / NAUG, n = id % NAUG;
    float v;
    if (n < 256) {
        v = W_q[k * 256 + n];
    } else if (n < 320) {
        const int j = n - 256;
        float s = 0.f;
        for (int i = 0; i < 256; i++) s = fmaf(W_q[k * 256 + i], W_off[i * 64 + j], s);
        v = s;
    } else if (n < 352) {
        const int j = n - 320;
        float s = 0.f;
        for (int i = 0; i < 256; i++) s = fmaf(W_q[k * 256 + i], W_attn[i * 32 + j], s);
        v = s;
    } else v = 0.f;
    W_aug[id] = v;
}

__global__ void prep_bias(const float* __restrict__ b_q, const float* __restrict__ b_off,
                          const float* __restrict__ b_attn,
                          const float* __restrict__ W_off, const float* __restrict__ W_attn,
                          float* __restrict__ b_aug)
{
    const int n = threadIdx.x;   // 384
    float v;
    if (n < 256) v = b_q[n];
    else if (n < 320) {
        const int j = n - 256;
        float s = b_off[j];
        for (int i = 0; i < 256; i++) s = fmaf(b_q[i], W_off[i * 64 + j], s);
        v = s;
    } else if (n < 352) {
        const int j = n - 320;
        float s = b_attn[j];
        for (int i = 0; i < 256; i++) s = fmaf(b_q[i], W_attn[i * 32 + j], s);
        v = s;
    } else v = 0.f;
    b_aug[n] = v;
}

// ---------------------------------------------------------------------------
// GEMM: C[4096 x N] = A[4096 x 256] @ W[256 x N] + bias (+ res)
// BM=128, BN=64, BK=16, 256 threads, 8x4 microtile.
// ---------------------------------------------------------------------------
__global__ __launch_bounds__(256)
void gemm_v2(const float* __restrict__ A, const float* __restrict__ W,
             const float* __restrict__ bias, const float* __restrict__ res, int ldres,
             float* __restrict__ C, int ldc, int ldw)
{
    __shared__ float As[16][132];
    __shared__ __align__(16) float Bs[16][64];

    const int tid = threadIdx.x;
    const int tx = tid & 15, ty = tid >> 4;
    const int n0 = blockIdx.x * 64;
    const int m0 = blockIdx.y * 128;

    float acc[8][4];
#pragma unroll
    for (int i = 0; i < 8; i++)
#pragma unroll
        for (int j = 0; j < 4; j++) acc[i][j] = 0.f;

    for (int k0 = 0; k0 < 256; k0 += 16) {
        {
            const int mr = tid >> 2;          // 0..63
            const int kq = (tid & 3) * 4;     // 0,4,8,12
#pragma unroll
            for (int r = 0; r < 2; r++) {
                const int m = mr + 64 * r;
                float4 v = *(const float4*)(A + (size_t)(m0 + m) * 256 + k0 + kq);
                As[kq + 0][m] = v.x; As[kq + 1][m] = v.y;
                As[kq + 2][m] = v.z; As[kq + 3][m] = v.w;
            }
        }
        {
            const int kr = tid >> 4;
            const int nq = (tid & 15) * 4;
            *(float4*)&Bs[kr][nq] = *(const float4*)(W + (size_t)(k0 + kr) * ldw + n0 + nq);
        }
        __syncthreads();

#pragma unroll
        for (int k = 0; k < 16; k++) {
            float a[8], b[4];
#pragma unroll
            for (int i = 0; i < 4; i++) {
                a[i]     = As[k][ty * 4 + i];
                a[i + 4] = As[k][64 + ty * 4 + i];
            }
#pragma unroll
            for (int j = 0; j < 4; j++) b[j] = Bs[k][tx * 4 + j];
#pragma unroll
            for (int i = 0; i < 8; i++)
#pragma unroll
                for (int j = 0; j < 4; j++)
                    acc[i][j] = fmaf(a[i], b[j], acc[i][j]);
        }
        __syncthreads();
    }

#pragma unroll
    for (int i = 0; i < 8; i++) {
        const int m = m0 + (i < 4 ? ty * 4 + i : 64 + ty * 4 + (i - 4));
#pragma unroll
        for (int j = 0; j < 4; j++) {
            const int n = n0 + tx * 4 + j;
            float v = acc[i][j] + bias[n];
            if (res) v += res[(size_t)m * ldres + n];
            C[(size_t)m * ldc + n] = v;
        }
    }
}

// ---------------------------------------------------------------------------
// Softmax over 4 logits per (row, head). 32768 threads.
// ---------------------------------------------------------------------------
__global__ __launch_bounds__(256)
void softmax_kernel(const float* __restrict__ qoa, float* __restrict__ attn)
{
    const int id = blockIdx.x * 256 + threadIdx.x;   // row*8 + h
    const int row = id >> 3, h = id & 7;
    float4 l = *(const float4*)(qoa + (size_t)row * NAUG + 320 + h * 4);
    float m = fmaxf(fmaxf(l.x, l.y), fmaxf(l.z, l.w));
    float e0 = expf(l.x - m), e1 = expf(l.y - m), e2 = expf(l.z - m), e3 = expf(l.w - m);
    float inv = 1.f / (e0 + e1 + e2 + e3);
    *(float4*)(attn + (size_t)row * 32 + h * 4) = make_float4(e0*inv, e1*inv, e2*inv, e3*inv);
}

// ---------------------------------------------------------------------------
// Corner precompute: one thread per (row, head, point). Writes 4 (idx, w).
// ---------------------------------------------------------------------------
__global__ __launch_bounds__(256)
void corners_kernel(const float* __restrict__ ctrl, const float* __restrict__ pcr,
                    const float* __restrict__ qoa, const float* __restrict__ attn,
                    int* __restrict__ cidx, float* __restrict__ cw)
{
    const int id = blockIdx.x * 256 + threadIdx.x;   // < 4096*32
    const int row = id >> 5, hp = id & 31, h = hp >> 2, p = hp & 3;

    const float lox = pcr[0], loy = pcr[1];
    const float spx = pcr[3] - pcr[0], spy = pcr[4] - pcr[1];
    const float* cp = ctrl + (size_t)row * 8;
    const float c0x = cp[0], c0y = cp[1], c1x = cp[2], c1y = cp[3];
    const float c2x = cp[4], c2y = cp[5], c3x = cp[6], c3y = cp[7];
    float sx = 0.f, sy = 0.f;
#pragma unroll
    for (int k = 0; k < 10; k++) {
        const float tt = (float)k / 9.0f;
        const float u = 1.0f - tt;
        const float w0 = u*u*u, w1 = 3.f*u*u*tt, w2 = 3.f*u*tt*tt, w3 = tt*tt*tt;
        const float dx = w0*c0x + w1*c1x + w2*c2x + w3*c3x;
        const float dy = w0*c0y + w1*c1y + w2*c2y + w3*c3y;
        sx += fminf(fmaxf((dx - lox) / spx, 0.01f), 0.99f);
        sy += fminf(fmaxf((dy - loy) / spy, 0.01f), 0.99f);
    }
    const float rcx = sx * 0.1f, rcy = sy * 0.1f;

    const float ox = qoa[(size_t)row * NAUG + 256 + h * 8 + p * 2 + 0];
    const float oy = qoa[(size_t)row * NAUG + 256 + h * 8 + p * 2 + 1];
    const float aw = attn[(size_t)row * 32 + hp];
    const float x = (rcx + ox / (float)GW) * (float)GW - 0.5f;
    const float y = (rcy + oy / (float)GH) * (float)GH - 0.5f;
    const float fx = floorf(x), fy = floorf(y);
    const int x0 = (int)fx, y0 = (int)fy;
    const int x1 = x0 + 1,  y1 = y0 + 1;
    const float wx = x - fx, wy = y - fy;
    const bool vx0 = (x0 >= 0) & (x0 < GW), vx1 = (x1 >= 0) & (x1 < GW);
    const bool vy0 = (y0 >= 0) & (y0 < GH), vy1 = (y1 >= 0) & (y1 < GH);
    const int cx0 = min(max(x0, 0), GW - 1), cx1 = min(max(x1, 0), GW - 1);
    const int cy0 = min(max(y0, 0), GH - 1), cy1 = min(max(y1, 0), GH - 1);

    int4  ci;
    float4 w;
    ci.x = cy0 * GW + cx0;  w.x = (vy0 & vx0) ? (1.f - wx) * (1.f - wy) * aw : 0.f;
    ci.y = cy0 * GW + cx1;  w.y = (vy0 & vx1) ? wx * (1.f - wy) * aw : 0.f;
    ci.z = cy1 * GW + cx0;  w.z = (vy1 & vx0) ? (1.f - wx) * wy * aw : 0.f;
    ci.w = cy1 * GW + cx1;  w.w = (vy1 & vx1) ? wx * wy * aw : 0.f;
    *(int4*)(cidx + (size_t)id * 4) = ci;
    *(float4*)(cw + (size_t)id * 4) = w;
}

// ---------------------------------------------------------------------------
// Transpose bev [B, C=256, HW] -> bevT [B, HW, C]. 32(C) x 64(HW) tiles, float4.
// ---------------------------------------------------------------------------
__global__ __launch_bounds__(256)
void transpose_kernel(const float* __restrict__ src, float* __restrict__ dst)
{
    __shared__ float tile[32 * 65];
    const int b  = blockIdx.z;
    const int p0 = blockIdx.x * 64;   // 40000/64 = 625
    const int c0 = blockIdx.y * 32;   // 256/32 = 8
    const int tid = threadIdx.x;

#pragma unroll
    for (int l = 0; l < 2; l++) {
        const int c = l * 16 + (tid >> 4);
        const int p = (tid & 15) * 4;
        float4 v = *(const float4*)(src + ((size_t)(b * 256 + c0 + c)) * NHW + p0 + p);
        tile[c * 65 + p + 0] = v.x;
        tile[c * 65 + p + 1] = v.y;
        tile[c * 65 + p + 2] = v.z;
        tile[c * 65 + p + 3] = v.w;
    }
    __syncthreads();

#pragma unroll
    for (int l = 0; l < 2; l++) {
        const int p  = l * 32 + (tid >> 3);
        const int cq = (tid & 7) * 4;
        float4 v;
        v.x = tile[(cq + 0) * 65 + p];
        v.y = tile[(cq + 1) * 65 + p];
        v.z = tile[(cq + 2) * 65 + p];
        v.w = tile[(cq + 3) * 65 + p];
        *(float4*)(dst + ((size_t)b * NHW + p0 + p) * 256 + c0 + cq) = v;
    }
}

// ---------------------------------------------------------------------------
// Fused gather + per-head projection. Block = (rowgroup of 64, head).
// W_val head-slice (256x32) cached in registers: thread (chunk=t>>5, d=t&31)
// holds W_val[chunk*32+j][h*32+d], j=0..31.
// ---------------------------------------------------------------------------
__global__ __launch_bounds__(256)
void fused_v2(const float* __restrict__ bevT,
              const int* __restrict__ cidx, const float* __restrict__ cw,
              const float* __restrict__ W_val, const float* __restrict__ b_val,
              float* __restrict__ samp)
{
    const int h  = blockIdx.y;
    const int r0 = blockIdx.x * 64;
    const int t  = threadIdx.x;
    const int d = t & 31, chunk = t >> 5;

    float Wreg[32];
#pragma unroll
    for (int j = 0; j < 32; j++)
        Wreg[j] = W_val[(size_t)(chunk * 32 + j) * 256 + h * 32 + d];
    const float bv = b_val[h * 32 + d];

    __shared__ int   ci[16];
    __shared__ float cws[16];
    __shared__ float gs[256];
    __shared__ float red[256];

    for (int r = 0; r < 64; r++) {
        const int row = r0 + r;
        const int b = row >> 10;
        if (t < 16) {
            ci[t]  = cidx[(size_t)row * 128 + h * 16 + t];
            cws[t] = cw  [(size_t)row * 128 + h * 16 + t];
        }
        __syncthreads();

        const float* base = bevT + ((size_t)b * NHW) * 256 + t;
        float acc = 0.f;
#pragma unroll
        for (int i = 0; i < 16; i++)
            acc = fmaf(cws[i], base[(size_t)ci[i] * 256], acc);
        gs[t] = acc;
        __syncthreads();

        float partial = 0.f;
#pragma unroll
        for (int j = 0; j < 32; j++)
            partial = fmaf(gs[chunk * 32 + j], Wreg[j], partial);
        red[t] = partial;
        __syncthreads();

        if (t < 32) {
            float s = 0.f;
#pragma unroll
            for (int i = 0; i < 16; i++) s += cws[i];
            float o = s * bv;
#pragma unroll
            for (int k = 0; k < 8; k++) o += red[k * 32 + t];
            samp[(size_t)row * 256 + h * 32 + t] = o;
        }
        __syncthreads();
    }
}

// ---------------------------------------------------------------------------
extern "C" void kernel_launch(void* const* d_in, const int* in_sizes, int n_in,
                              void* d_out, int out_size)
{
    const float* query_embed = (const float*)d_in[0];
    const float* ctrl        = (const float*)d_in[1];
    const float* bev         = (const float*)d_in[2];
    /* d_in[3] spatial_shapes unused */
    const float* pc_range    = (const float*)d_in[4];
    const float* W_q   = (const float*)d_in[5];
    const float* b_q   = (const float*)d_in[6];
    const float* W_val = (const float*)d_in[7];
    const float* b_val = (const float*)d_in[8];
    const float* W_off = (const float*)d_in[9];
    const float* b_off = (const float*)d_in[10];
    const float* W_attn = (const float*)d_in[11];
    const float* b_attn = (const float*)d_in[12];
    const float* W_do  = (const float*)d_in[13];
    const float* b_do  = (const float*)d_in[14];
    const float* W_out = (const float*)d_in[15];
    const float* b_out = (const float*)d_in[16];
    float* out = (float*)d_out;

    float *pqoa, *pWaug, *pbaug, *pa, *pcw, *pbT, *ps, *pm;
    int *pci;
    cudaGetSymbolAddress((void**)&pqoa,  g_qoa);
    cudaGetSymbolAddress((void**)&pWaug, g_Waug);
    cudaGetSymbolAddress((void**)&pbaug, g_baug);
    cudaGetSymbolAddress((void**)&pa,    g_attn);
    cudaGetSymbolAddress((void**)&pci,   g_cidx);
    cudaGetSymbolAddress((void**)&pcw,   g_cw);
    cudaGetSymbolAddress((void**)&pbT,   g_bevT);
    cudaGetSymbolAddress((void**)&ps,    g_samp);
    cudaGetSymbolAddress((void**)&pm,    g_msda);

    // 0) compose augmented projection weights
    prep_weights<<<(DIM * NAUG) / 256, 256>>>(W_q, W_off, W_attn, pWaug);
    prep_bias<<<1, NAUG>>>(b_q, b_off, b_attn, W_off, W_attn, pbaug);

    // 1) [query | offsets | logits] = qe @ W_aug + b_aug
    gemm_v2<<<dim3(NAUG / 64, NROWS / 128), 256>>>(
        query_embed, pWaug, pbaug, nullptr, 0, pqoa, NAUG, NAUG);

    // 2) softmax over logits
    softmax_kernel<<<(NROWS * 8) / 256, 256>>>(pqoa, pa);

    // 3) corner indices/weights
    corners_kernel<<<(NROWS * 32) / 256, 256>>>(ctrl, pc_range, pqoa, pa, pci, pcw);

    // 4) transpose bev -> bevT [B, HW, C]
    transpose_kernel<<<dim3(NHW / 64, DIM / 32, NB), 256>>>(bev, pbT);

    // 5) fused gather + per-head value projection
    fused_v2<<<dim3(NROWS / 64, NHEADS), 256>>>(pbT, pci, pcw, W_val, b_val, ps);

    // 6) msda = samp @ W_do + b_do + query(qoa cols 0..255)
    gemm_v2<<<dim3(DIM / 64, NROWS / 128), 256>>>(
        ps, W_do, b_do, pqoa, NAUG, pm, DIM, DIM);

    // 7) out = msda @ W_out + b_out
    gemm_v2<<<dim3(DIM / 64, NROWS / 128), 256>>>(
        pm, W_out, b_out, nullptr, 0, out, DIM, DIM);
}

// round 4
// speedup vs baseline: 1.1637x; 1.1637x over previous
#include <cuda_runtime.h>
#include <math.h>

#define NB     4
#define NQ     1024
#define DIM    256
#define NHEADS 8
#define GH     200
#define GW     200
#define NHW    (GH*GW)       // 40000
#define NROWS  (NB*NQ)       // 4096
#define NAUG   384           // 256 query | 64 off | 32 attn logits | 32 pad

// Scratch (__device__ globals: allocation-free per harness rules)
__device__ float g_qoa  [NROWS * NAUG];
__device__ float g_Waug [DIM * NAUG];
__device__ float g_baug [NAUG];
__device__ float g_gath [(size_t)NROWS * NHEADS * DIM];  // 32 MB
__device__ float g_wsum [NROWS * NHEADS];
__device__ float g_bevT [(size_t)NB * NHW * DIM];        // 164 MB
__device__ float g_samp [NROWS * DIM];
__device__ float g_msda [NROWS * DIM];

// ---------------------------------------------------------------------------
// W_aug = [ W_q | W_q@W_off | W_q@W_attn | 0 ],  b_aug analogous
// ---------------------------------------------------------------------------
__global__ __launch_bounds__(256)
void prep_weights(const float* __restrict__ W_q, const float* __restrict__ W_off,
                  const float* __restrict__ W_attn, float* __restrict__ W_aug)
{
    const int id = blockIdx.x * 256 + threadIdx.x;   // 256*384
    const int k = id / NAUG, n = id % NAUG;
    float v;
    if (n < 256) {
        v = W_q[k * 256 + n];
    } else if (n < 320) {
        const int j = n - 256;
        float s = 0.f;
        for (int i = 0; i < 256; i++) s = fmaf(W_q[k * 256 + i], W_off[i * 64 + j], s);
        v = s;
    } else if (n < 352) {
        const int j = n - 320;
        float s = 0.f;
        for (int i = 0; i < 256; i++) s = fmaf(W_q[k * 256 + i], W_attn[i * 32 + j], s);
        v = s;
    } else v = 0.f;
    W_aug[id] = v;
}

__global__ void prep_bias(const float* __restrict__ b_q, const float* __restrict__ b_off,
                          const float* __restrict__ b_attn,
                          const float* __restrict__ W_off, const float* __restrict__ W_attn,
                          float* __restrict__ b_aug)
{
    const int n = threadIdx.x;   // 384
    float v;
    if (n < 256) v = b_q[n];
    else if (n < 320) {
        const int j = n - 256;
        float s = b_off[j];
        for (int i = 0; i < 256; i++) s = fmaf(b_q[i], W_off[i * 64 + j], s);
        v = s;
    } else if (n < 352) {
        const int j = n - 320;
        float s = b_attn[j];
        for (int i = 0; i < 256; i++) s = fmaf(b_q[i], W_attn[i * 32 + j], s);
        v = s;
    } else v = 0.f;
    b_aug[n] = v;
}

// ---------------------------------------------------------------------------
// GEMM: C[4096 x N] = A[4096 x 256] @ W[256 x N] + bias (+ res)
// BM=128, BN=64, BK=16, 256 threads, 8x4 microtile.
// ---------------------------------------------------------------------------
__global__ __launch_bounds__(256)
void gemm_v2(const float* __restrict__ A, const float* __restrict__ W,
             const float* __restrict__ bias, const float* __restrict__ res, int ldres,
             float* __restrict__ C, int ldc, int ldw)
{
    __shared__ float As[16][132];
    __shared__ __align__(16) float Bs[16][64];

    const int tid = threadIdx.x;
    const int tx = tid & 15, ty = tid >> 4;
    const int n0 = blockIdx.x * 64;
    const int m0 = blockIdx.y * 128;

    float acc[8][4];
#pragma unroll
    for (int i = 0; i < 8; i++)
#pragma unroll
        for (int j = 0; j < 4; j++) acc[i][j] = 0.f;

    for (int k0 = 0; k0 < 256; k0 += 16) {
        {
            const int mr = tid >> 2;
            const int kq = (tid & 3) * 4;
#pragma unroll
            for (int r = 0; r < 2; r++) {
                const int m = mr + 64 * r;
                float4 v = *(const float4*)(A + (size_t)(m0 + m) * 256 + k0 + kq);
                As[kq + 0][m] = v.x; As[kq + 1][m] = v.y;
                As[kq + 2][m] = v.z; As[kq + 3][m] = v.w;
            }
        }
        {
            const int kr = tid >> 4;
            const int nq = (tid & 15) * 4;
            *(float4*)&Bs[kr][nq] = *(const float4*)(W + (size_t)(k0 + kr) * ldw + n0 + nq);
        }
        __syncthreads();

#pragma unroll
        for (int k = 0; k < 16; k++) {
            float a[8], b[4];
#pragma unroll
            for (int i = 0; i < 4; i++) {
                a[i]     = As[k][ty * 4 + i];
                a[i + 4] = As[k][64 + ty * 4 + i];
            }
#pragma unroll
            for (int j = 0; j < 4; j++) b[j] = Bs[k][tx * 4 + j];
#pragma unroll
            for (int i = 0; i < 8; i++)
#pragma unroll
                for (int j = 0; j < 4; j++)
                    acc[i][j] = fmaf(a[i], b[j], acc[i][j]);
        }
        __syncthreads();
    }

#pragma unroll
    for (int i = 0; i < 8; i++) {
        const int m = m0 + (i < 4 ? ty * 4 + i : 64 + ty * 4 + (i - 4));
#pragma unroll
        for (int j = 0; j < 4; j++) {
            const int n = n0 + tx * 4 + j;
            float v = acc[i][j] + bias[n];
            if (res) v += res[(size_t)m * ldres + n];
            C[(size_t)m * ldc + n] = v;
        }
    }
}

// ---------------------------------------------------------------------------
// Transpose bev [B, C=256, HW] -> bevT [B, HW, C]. 32(C) x 64(HW) tiles, float4.
// ---------------------------------------------------------------------------
__global__ __launch_bounds__(256)
void transpose_kernel(const float* __restrict__ src, float* __restrict__ dst)
{
    __shared__ float tile[32 * 65];
    const int b  = blockIdx.z;
    const int p0 = blockIdx.x * 64;
    const int c0 = blockIdx.y * 32;
    const int tid = threadIdx.x;

#pragma unroll
    for (int l = 0; l < 2; l++) {
        const int c = l * 16 + (tid >> 4);
        const int p = (tid & 15) * 4;
        float4 v = *(const float4*)(src + ((size_t)(b * 256 + c0 + c)) * NHW + p0 + p);
        tile[c * 65 + p + 0] = v.x;
        tile[c * 65 + p + 1] = v.y;
        tile[c * 65 + p + 2] = v.z;
        tile[c * 65 + p + 3] = v.w;
    }
    __syncthreads();

#pragma unroll
    for (int l = 0; l < 2; l++) {
        const int p  = l * 32 + (tid >> 3);
        const int cq = (tid & 7) * 4;
        float4 v;
        v.x = tile[(cq + 0) * 65 + p];
        v.y = tile[(cq + 1) * 65 + p];
        v.z = tile[(cq + 2) * 65 + p];
        v.w = tile[(cq + 3) * 65 + p];
        *(float4*)(dst + ((size_t)b * NHW + p0 + p) * 256 + c0 + cq) = v;
    }
}

// ---------------------------------------------------------------------------
// Gather: Bezier + softmax + corners (lanes t<32), then weighted raw-feature
// sum per head. One block per row; thread t = channel. Writes g[row*8+h][256].
// ---------------------------------------------------------------------------
__global__ __launch_bounds__(256)
void gather_kernel(const float* __restrict__ ctrl, const float* __restrict__ pcr,
                   const float* __restrict__ bevT, const float* __restrict__ qoa,
                   float* __restrict__ g, float* __restrict__ wsum)
{
    const int row = blockIdx.x;
    const int b = row >> 10;
    const int t = threadIdx.x;

    __shared__ int   cidx[32][4];
    __shared__ float cw  [32][4];
    __shared__ float ws  [32];

    if (t < 32) {
        const float lox = pcr[0], loy = pcr[1];
        const float spx = pcr[3] - pcr[0], spy = pcr[4] - pcr[1];
        const float* cp = ctrl + (size_t)row * 8;
        const float c0x = cp[0], c0y = cp[1], c1x = cp[2], c1y = cp[3];
        const float c2x = cp[4], c2y = cp[5], c3x = cp[6], c3y = cp[7];
        float sx = 0.f, sy = 0.f;
#pragma unroll
        for (int k = 0; k < 10; k++) {
            const float tt = (float)k / 9.0f;
            const float u = 1.0f - tt;
            const float w0 = u*u*u, w1 = 3.f*u*u*tt, w2 = 3.f*u*tt*tt, w3 = tt*tt*tt;
            const float dx = w0*c0x + w1*c1x + w2*c2x + w3*c3x;
            const float dy = w0*c0y + w1*c1y + w2*c2y + w3*c3y;
            sx += fminf(fmaxf((dx - lox) / spx, 0.01f), 0.99f);
            sy += fminf(fmaxf((dy - loy) / spy, 0.01f), 0.99f);
        }
        const float rcx = sx * 0.1f, rcy = sy * 0.1f;

        const int h = t >> 2, p = t & 3;
        // softmax over this head's 4 logits (each lane recomputes; cheap)
        const float* lg = qoa + (size_t)row * NAUG + 320 + h * 4;
        const float l0 = lg[0], l1 = lg[1], l2 = lg[2], l3 = lg[3];
        const float m = fmaxf(fmaxf(l0, l1), fmaxf(l2, l3));
        const float e0 = expf(l0 - m), e1 = expf(l1 - m), e2 = expf(l2 - m), e3 = expf(l3 - m);
        const float lp = (p == 0) ? l0 : (p == 1) ? l1 : (p == 2) ? l2 : l3;
        const float aw = expf(lp - m) / (e0 + e1 + e2 + e3);

        const float ox = qoa[(size_t)row * NAUG + 256 + h * 8 + p * 2 + 0];
        const float oy = qoa[(size_t)row * NAUG + 256 + h * 8 + p * 2 + 1];
        const float x = (rcx + ox / (float)GW) * (float)GW - 0.5f;
        const float y = (rcy + oy / (float)GH) * (float)GH - 0.5f;
        const float fx = floorf(x), fy = floorf(y);
        const int x0 = (int)fx, y0 = (int)fy;
        const int x1 = x0 + 1,  y1 = y0 + 1;
        const float wx = x - fx, wy = y - fy;
        const bool vx0 = (x0 >= 0) & (x0 < GW), vx1 = (x1 >= 0) & (x1 < GW);
        const bool vy0 = (y0 >= 0) & (y0 < GH), vy1 = (y1 >= 0) & (y1 < GH);
        const int cx0 = min(max(x0, 0), GW - 1), cx1 = min(max(x1, 0), GW - 1);
        const int cy0 = min(max(y0, 0), GH - 1), cy1 = min(max(y1, 0), GH - 1);
        const float w00 = (vy0 & vx0) ? (1.f - wx) * (1.f - wy) * aw : 0.f;
        const float w01 = (vy0 & vx1) ? wx * (1.f - wy) * aw : 0.f;
        const float w10 = (vy1 & vx0) ? (1.f - wx) * wy * aw : 0.f;
        const float w11 = (vy1 & vx1) ? wx * wy * aw : 0.f;
        cidx[t][0] = cy0 * GW + cx0;  cw[t][0] = w00;
        cidx[t][1] = cy0 * GW + cx1;  cw[t][1] = w01;
        cidx[t][2] = cy1 * GW + cx0;  cw[t][2] = w10;
        cidx[t][3] = cy1 * GW + cx1;  cw[t][3] = w11;
        ws[t] = w00 + w01 + w10 + w11;
    }
    __syncthreads();

    const float* base = bevT + ((size_t)b * NHW) * 256 + t;
    float acc[8];
#pragma unroll
    for (int h = 0; h < 8; h++) acc[h] = 0.f;
#pragma unroll
    for (int hp = 0; hp < 32; hp++) {
        float a = 0.f;
#pragma unroll
        for (int c = 0; c < 4; c++)
            a = fmaf(cw[hp][c], base[(size_t)cidx[hp][c] * 256], a);
        acc[hp >> 2] += a;
    }
#pragma unroll
    for (int h = 0; h < 8; h++)
        g[((size_t)row * 8 + h) * 256 + t] = acc[h];

    if (t < 8)
        wsum[(size_t)row * 8 + t] = ws[t*4] + ws[t*4+1] + ws[t*4+2] + ws[t*4+3];
}

// ---------------------------------------------------------------------------
// Block-diagonal projection: samp[row][h*32+d] = g[row*8+h] . W_val[:,h*32+d]
//                                              + wsum[row,h]*b_val[h*32+d]
// Block = (128 rows, head). W slice (256x32) in smem; A tiled by K=32.
// ---------------------------------------------------------------------------
__global__ __launch_bounds__(256)
void proj_kernel(const float* __restrict__ g, const float* __restrict__ wsum,
                 const float* __restrict__ W_val, const float* __restrict__ b_val,
                 float* __restrict__ samp)
{
    const int h  = blockIdx.y;
    const int r0 = blockIdx.x * 128;
    const int t  = threadIdx.x;
    const int d = t & 31, rg = t >> 5;

    __shared__ float Ws[256 * 32];
    __shared__ float As[128 * 36];

    // load W_val[:, h*32 + 0..31] -> Ws[k][d]
#pragma unroll
    for (int i = 0; i < 32; i++) {
        const int k = i * 8 + (t >> 5);
        Ws[k * 32 + d] = W_val[(size_t)k * 256 + h * 32 + d];
    }
    const float bv = b_val[h * 32 + d];

    float acc[16];
#pragma unroll
    for (int r = 0; r < 16; r++) acc[r] = 0.f;

    for (int kt = 0; kt < 8; kt++) {
        __syncthreads();
        {
            const int i = t >> 1, half = t & 1;
            const float* src = g + ((size_t)(r0 + i) * 8 + h) * 256 + kt * 32 + half * 16;
            float* dst = &As[i * 36 + half * 16];
#pragma unroll
            for (int q = 0; q < 4; q++)
                *(float4*)(dst + q * 4) = *(const float4*)(src + q * 4);
        }
        __syncthreads();

#pragma unroll
        for (int k = 0; k < 32; k++) {
            const float wv = Ws[(kt * 32 + k) * 32 + d];
#pragma unroll
            for (int r = 0; r < 16; r++)
                acc[r] = fmaf(As[(rg * 16 + r) * 36 + k], wv, acc[r]);
        }
    }

#pragma unroll
    for (int r = 0; r < 16; r++) {
        const int row = r0 + rg * 16 + r;
        samp[(size_t)row * 256 + h * 32 + d] = acc[r] + wsum[(size_t)row * 8 + h] * bv;
    }
}

// ---------------------------------------------------------------------------
extern "C" void kernel_launch(void* const* d_in, const int* in_sizes, int n_in,
                              void* d_out, int out_size)
{
    const float* query_embed = (const float*)d_in[0];
    const float* ctrl        = (const float*)d_in[1];
    const float* bev         = (const float*)d_in[2];
    /* d_in[3] spatial_shapes unused */
    const float* pc_range    = (const float*)d_in[4];
    const float* W_q   = (const float*)d_in[5];
    const float* b_q   = (const float*)d_in[6];
    const float* W_val = (const float*)d_in[7];
    const float* b_val = (const float*)d_in[8];
    const float* W_off = (const float*)d_in[9];
    const float* b_off = (const float*)d_in[10];
    const float* W_attn = (const float*)d_in[11];
    const float* b_attn = (const float*)d_in[12];
    const float* W_do  = (const float*)d_in[13];
    const float* b_do  = (const float*)d_in[14];
    const float* W_out = (const float*)d_in[15];
    const float* b_out = (const float*)d_in[16];
    float* out = (float*)d_out;

    float *pqoa, *pWaug, *pbaug, *pg, *pws, *pbT, *ps, *pm;
    cudaGetSymbolAddress((void**)&pqoa,  g_qoa);
    cudaGetSymbolAddress((void**)&pWaug, g_Waug);
    cudaGetSymbolAddress((void**)&pbaug, g_baug);
    cudaGetSymbolAddress((void**)&pg,    g_gath);
    cudaGetSymbolAddress((void**)&pws,   g_wsum);
    cudaGetSymbolAddress((void**)&pbT,   g_bevT);
    cudaGetSymbolAddress((void**)&ps,    g_samp);
    cudaGetSymbolAddress((void**)&pm,    g_msda);

    // 0) augmented projection weights
    prep_weights<<<(DIM * NAUG) / 256, 256>>>(W_q, W_off, W_attn, pWaug);
    prep_bias<<<1, NAUG>>>(b_q, b_off, b_attn, W_off, W_attn, pbaug);

    // 1) [query | offsets | logits] = qe @ W_aug + b_aug
    gemm_v2<<<dim3(NAUG / 64, NROWS / 128), 256>>>(
        query_embed, pWaug, pbaug, nullptr, 0, pqoa, NAUG, NAUG);

    // 2) transpose bev -> bevT [B, HW, C]
    transpose_kernel<<<dim3(NHW / 64, DIM / 32, NB), 256>>>(bev, pbT);

    // 3) gather raw features (corners + softmax inline)
    gather_kernel<<<NROWS, 256>>>(ctrl, pc_range, pbT, pqoa, pg, pws);

    // 4) per-head projection (block-diagonal small GEMM)
    proj_kernel<<<dim3(NROWS / 128, NHEADS), 256>>>(pg, pws, W_val, b_val, ps);

    // 5) msda = samp @ W_do + b_do + query
    gemm_v2<<<dim3(DIM / 64, NROWS / 128), 256>>>(
        ps, W_do, b_do, pqoa, NAUG, pm, DIM, DIM);

    // 6) out = msda @ W_out + b_out
    gemm_v2<<<dim3(DIM / 64, NROWS / 128), 256>>>(
        pm, W_out, b_out, nullptr, 0, out, DIM, DIM);
}

// round 5
// speedup vs baseline: 1.2477x; 1.0722x over previous
#include <cuda_runtime.h>
#include <math.h>

#define NB     4
#define NQ     1024
#define DIM    256
#define NHEADS 8
#define GH     200
#define GW     200
#define NHW    (GH*GW)       // 40000
#define NROWS  (NB*NQ)       // 4096
#define NAUG   384           // 256 query | 64 off | 32 attn logits | 32 pad

// Scratch (__device__ globals: allocation-free per harness rules)
__device__ float g_qoa  [NROWS * NAUG];
__device__ float g_Waug [DIM * NAUG];
__device__ float g_baug [NAUG];
__device__ float g_gath [(size_t)NROWS * NHEADS * DIM];  // 32 MB
__device__ float g_wsum [NROWS * NHEADS];
__device__ float g_bevT [(size_t)NB * NHW * DIM];        // 164 MB
__device__ float g_samp [NROWS * DIM];
__device__ float g_msda [NROWS * DIM];

// ---------------------------------------------------------------------------
// W_aug = [ W_q | W_q@W_off | W_q@W_attn | 0 ],  b_aug analogous
// ---------------------------------------------------------------------------
__global__ __launch_bounds__(256)
void prep_weights(const float* __restrict__ W_q, const float* __restrict__ W_off,
                  const float* __restrict__ W_attn, float* __restrict__ W_aug)
{
    const int id = blockIdx.x * 256 + threadIdx.x;   // 256*384
    const int k = id / NAUG, n = id % NAUG;
    float v;
    if (n < 256) {
        v = W_q[k * 256 + n];
    } else if (n < 320) {
        const int j = n - 256;
        float s = 0.f;
        for (int i = 0; i < 256; i++) s = fmaf(W_q[k * 256 + i], W_off[i * 64 + j], s);
        v = s;
    } else if (n < 352) {
        const int j = n - 320;
        float s = 0.f;
        for (int i = 0; i < 256; i++) s = fmaf(W_q[k * 256 + i], W_attn[i * 32 + j], s);
        v = s;
    } else v = 0.f;
    W_aug[id] = v;
}

__global__ void prep_bias(const float* __restrict__ b_q, const float* __restrict__ b_off,
                          const float* __restrict__ b_attn,
                          const float* __restrict__ W_off, const float* __restrict__ W_attn,
                          float* __restrict__ b_aug)
{
    const int n = threadIdx.x;   // 384
    float v;
    if (n < 256) v = b_q[n];
    else if (n < 320) {
        const int j = n - 256;
        float s = b_off[j];
        for (int i = 0; i < 256; i++) s = fmaf(b_q[i], W_off[i * 64 + j], s);
        v = s;
    } else if (n < 352) {
        const int j = n - 320;
        float s = b_attn[j];
        for (int i = 0; i < 256; i++) s = fmaf(b_q[i], W_attn[i * 32 + j], s);
        v = s;
    } else v = 0.f;
    b_aug[n] = v;
}

// ---------------------------------------------------------------------------
// GEMM: C[4096 x N] = A[4096 x 256] @ W[256 x N] + bias (+ res)
// BM=128, BN=64, BK=16, 256 threads, 8x4 microtile.
// ---------------------------------------------------------------------------
__global__ __launch_bounds__(256)
void gemm_v2(const float* __restrict__ A, const float* __restrict__ W,
             const float* __restrict__ bias, const float* __restrict__ res, int ldres,
             float* __restrict__ C, int ldc, int ldw)
{
    __shared__ float As[16][132];
    __shared__ __align__(16) float Bs[16][64];

    const int tid = threadIdx.x;
    const int tx = tid & 15, ty = tid >> 4;
    const int n0 = blockIdx.x * 64;
    const int m0 = blockIdx.y * 128;

    float acc[8][4];
#pragma unroll
    for (int i = 0; i < 8; i++)
#pragma unroll
        for (int j = 0; j < 4; j++) acc[i][j] = 0.f;

    for (int k0 = 0; k0 < 256; k0 += 16) {
        {
            const int mr = tid >> 2;
            const int kq = (tid & 3) * 4;
#pragma unroll
            for (int r = 0; r < 2; r++) {
                const int m = mr + 64 * r;
                float4 v = *(const float4*)(A + (size_t)(m0 + m) * 256 + k0 + kq);
                As[kq + 0][m] = v.x; As[kq + 1][m] = v.y;
                As[kq + 2][m] = v.z; As[kq + 3][m] = v.w;
            }
        }
        {
            const int kr = tid >> 4;
            const int nq = (tid & 15) * 4;
            *(float4*)&Bs[kr][nq] = *(const float4*)(W + (size_t)(k0 + kr) * ldw + n0 + nq);
        }
        __syncthreads();

#pragma unroll
        for (int k = 0; k < 16; k++) {
            float a[8], b[4];
#pragma unroll
            for (int i = 0; i < 4; i++) {
                a[i]     = As[k][ty * 4 + i];
                a[i + 4] = As[k][64 + ty * 4 + i];
            }
#pragma unroll
            for (int j = 0; j < 4; j++) b[j] = Bs[k][tx * 4 + j];
#pragma unroll
            for (int i = 0; i < 8; i++)
#pragma unroll
                for (int j = 0; j < 4; j++)
                    acc[i][j] = fmaf(a[i], b[j], acc[i][j]);
        }
        __syncthreads();
    }

#pragma unroll
    for (int i = 0; i < 8; i++) {
        const int m = m0 + (i < 4 ? ty * 4 + i : 64 + ty * 4 + (i - 4));
#pragma unroll
        for (int j = 0; j < 4; j++) {
            const int n = n0 + tx * 4 + j;
            float v = acc[i][j] + bias[n];
            if (res) v += res[(size_t)m * ldres + n];
            C[(size_t)m * ldc + n] = v;
        }
    }
}

// ---------------------------------------------------------------------------
// Transpose bev [B, C=256, HW] -> bevT [B, HW, C]. 32(C) x 64(HW) tiles, float4.
// ---------------------------------------------------------------------------
__global__ __launch_bounds__(256)
void transpose_kernel(const float* __restrict__ src, float* __restrict__ dst)
{
    __shared__ float tile[32 * 65];
    const int b  = blockIdx.z;
    const int p0 = blockIdx.x * 64;
    const int c0 = blockIdx.y * 32;
    const int tid = threadIdx.x;

#pragma unroll
    for (int l = 0; l < 2; l++) {
        const int c = l * 16 + (tid >> 4);
        const int p = (tid & 15) * 4;
        float4 v = *(const float4*)(src + ((size_t)(b * 256 + c0 + c)) * NHW + p0 + p);
        tile[c * 65 + p + 0] = v.x;
        tile[c * 65 + p + 1] = v.y;
        tile[c * 65 + p + 2] = v.z;
        tile[c * 65 + p + 3] = v.w;
    }
    __syncthreads();

#pragma unroll
    for (int l = 0; l < 2; l++) {
        const int p  = l * 32 + (tid >> 3);
        const int cq = (tid & 7) * 4;
        float4 v;
        v.x = tile[(cq + 0) * 65 + p];
        v.y = tile[(cq + 1) * 65 + p];
        v.z = tile[(cq + 2) * 65 + p];
        v.w = tile[(cq + 3) * 65 + p];
        *(float4*)(dst + ((size_t)b * NHW + p0 + p) * 256 + c0 + cq) = v;
    }
}

// ---------------------------------------------------------------------------
// Gather: Bezier + softmax + corners (lanes t<32), then weighted raw-feature
// sum per head using float4 channel quads.
// Block per row; thread t = (channel-quad cq = t&63, head-group hg = t>>6).
// ---------------------------------------------------------------------------
__global__ __launch_bounds__(256)
void gather_kernel(const float* __restrict__ ctrl, const float* __restrict__ pcr,
                   const float* __restrict__ bevT, const float* __restrict__ qoa,
                   float* __restrict__ g, float* __restrict__ wsum)
{
    const int row = blockIdx.x;
    const int b = row >> 10;
    const int t = threadIdx.x;

    __shared__ int   cidx[32][4];
    __shared__ float cw  [32][4];
    __shared__ float ws  [32];

    if (t < 32) {
        const float lox = pcr[0], loy = pcr[1];
        const float spx = pcr[3] - pcr[0], spy = pcr[4] - pcr[1];
        const float* cp = ctrl + (size_t)row * 8;
        const float c0x = cp[0], c0y = cp[1], c1x = cp[2], c1y = cp[3];
        const float c2x = cp[4], c2y = cp[5], c3x = cp[6], c3y = cp[7];
        float sx = 0.f, sy = 0.f;
#pragma unroll
        for (int k = 0; k < 10; k++) {
            const float tt = (float)k / 9.0f;
            const float u = 1.0f - tt;
            const float w0 = u*u*u, w1 = 3.f*u*u*tt, w2 = 3.f*u*tt*tt, w3 = tt*tt*tt;
            const float dx = w0*c0x + w1*c1x + w2*c2x + w3*c3x;
            const float dy = w0*c0y + w1*c1y + w2*c2y + w3*c3y;
            sx += fminf(fmaxf((dx - lox) / spx, 0.01f), 0.99f);
            sy += fminf(fmaxf((dy - loy) / spy, 0.01f), 0.99f);
        }
        const float rcx = sx * 0.1f, rcy = sy * 0.1f;

        const int h = t >> 2, p = t & 3;
        const float* lg = qoa + (size_t)row * NAUG + 320 + h * 4;
        const float l0 = lg[0], l1 = lg[1], l2 = lg[2], l3 = lg[3];
        const float m = fmaxf(fmaxf(l0, l1), fmaxf(l2, l3));
        const float e0 = expf(l0 - m), e1 = expf(l1 - m), e2 = expf(l2 - m), e3 = expf(l3 - m);
        const float lp = (p == 0) ? l0 : (p == 1) ? l1 : (p == 2) ? l2 : l3;
        const float aw = expf(lp - m) / (e0 + e1 + e2 + e3);

        const float ox = qoa[(size_t)row * NAUG + 256 + h * 8 + p * 2 + 0];
        const float oy = qoa[(size_t)row * NAUG + 256 + h * 8 + p * 2 + 1];
        const float x = (rcx + ox / (float)GW) * (float)GW - 0.5f;
        const float y = (rcy + oy / (float)GH) * (float)GH - 0.5f;
        const float fx = floorf(x), fy = floorf(y);
        const int x0 = (int)fx, y0 = (int)fy;
        const int x1 = x0 + 1,  y1 = y0 + 1;
        const float wx = x - fx, wy = y - fy;
        const bool vx0 = (x0 >= 0) & (x0 < GW), vx1 = (x1 >= 0) & (x1 < GW);
        const bool vy0 = (y0 >= 0) & (y0 < GH), vy1 = (y1 >= 0) & (y1 < GH);
        const int cx0 = min(max(x0, 0), GW - 1), cx1 = min(max(x1, 0), GW - 1);
        const int cy0 = min(max(y0, 0), GH - 1), cy1 = min(max(y1, 0), GH - 1);
        const float w00 = (vy0 & vx0) ? (1.f - wx) * (1.f - wy) * aw : 0.f;
        const float w01 = (vy0 & vx1) ? wx * (1.f - wy) * aw : 0.f;
        const float w10 = (vy1 & vx0) ? (1.f - wx) * wy * aw : 0.f;
        const float w11 = (vy1 & vx1) ? wx * wy * aw : 0.f;
        cidx[t][0] = cy0 * GW + cx0;  cw[t][0] = w00;
        cidx[t][1] = cy0 * GW + cx1;  cw[t][1] = w01;
        cidx[t][2] = cy1 * GW + cx0;  cw[t][2] = w10;
        cidx[t][3] = cy1 * GW + cx1;  cw[t][3] = w11;
        ws[t] = w00 + w01 + w10 + w11;
    }
    __syncthreads();

    const int cq = t & 63;            // channel quad 0..63
    const int hg = t >> 6;            // head group 0..3 -> heads {2hg, 2hg+1}
    const float* base = bevT + ((size_t)b * NHW) * 256 + cq * 4;

#pragma unroll
    for (int e = 0; e < 2; e++) {
        const int h = hg * 2 + e;
        float4 acc = make_float4(0.f, 0.f, 0.f, 0.f);
#pragma unroll
        for (int p = 0; p < 4; p++) {
            const int hp = h * 4 + p;
#pragma unroll
            for (int c2 = 0; c2 < 4; c2++) {
                const float w = cw[hp][c2];
                const float4 v = *(const float4*)(base + (size_t)cidx[hp][c2] * 256);
                acc.x = fmaf(w, v.x, acc.x);
                acc.y = fmaf(w, v.y, acc.y);
                acc.z = fmaf(w, v.z, acc.z);
                acc.w = fmaf(w, v.w, acc.w);
            }
        }
        *(float4*)(g + ((size_t)row * 8 + h) * 256 + cq * 4) = acc;
    }

    if (t < 8)
        wsum[(size_t)row * 8 + t] = ws[t*4] + ws[t*4+1] + ws[t*4+2] + ws[t*4+3];
}

// ---------------------------------------------------------------------------
// Block-diagonal projection: samp[row][h*32+d] = g[row*8+h] . W_val[:,h*32+d]
//                                              + wsum[row,h]*b_val[h*32+d]
// ---------------------------------------------------------------------------
__global__ __launch_bounds__(256)
void proj_kernel(const float* __restrict__ g, const float* __restrict__ wsum,
                 const float* __restrict__ W_val, const float* __restrict__ b_val,
                 float* __restrict__ samp)
{
    const int h  = blockIdx.y;
    const int r0 = blockIdx.x * 128;
    const int t  = threadIdx.x;
    const int d = t & 31, rg = t >> 5;

    __shared__ float Ws[256 * 32];
    __shared__ float As[128 * 36];

#pragma unroll
    for (int i = 0; i < 32; i++) {
        const int k = i * 8 + (t >> 5);
        Ws[k * 32 + d] = W_val[(size_t)k * 256 + h * 32 + d];
    }
    const float bv = b_val[h * 32 + d];

    float acc[16];
#pragma unroll
    for (int r = 0; r < 16; r++) acc[r] = 0.f;

    for (int kt = 0; kt < 8; kt++) {
        __syncthreads();
        {
            const int i = t >> 1, half = t & 1;
            const float* src = g + ((size_t)(r0 + i) * 8 + h) * 256 + kt * 32 + half * 16;
            float* dst = &As[i * 36 + half * 16];
#pragma unroll
            for (int q = 0; q < 4; q++)
                *(float4*)(dst + q * 4) = *(const float4*)(src + q * 4);
        }
        __syncthreads();

#pragma unroll
        for (int k = 0; k < 32; k++) {
            const float wv = Ws[(kt * 32 + k) * 32 + d];
#pragma unroll
            for (int r = 0; r < 16; r++)
                acc[r] = fmaf(As[(rg * 16 + r) * 36 + k], wv, acc[r]);
        }
    }

#pragma unroll
    for (int r = 0; r < 16; r++) {
        const int row = r0 + rg * 16 + r;
        samp[(size_t)row * 256 + h * 32 + d] = acc[r] + wsum[(size_t)row * 8 + h] * bv;
    }
}

// ---------------------------------------------------------------------------
extern "C" void kernel_launch(void* const* d_in, const int* in_sizes, int n_in,
                              void* d_out, int out_size)
{
    const float* query_embed = (const float*)d_in[0];
    const float* ctrl        = (const float*)d_in[1];
    const float* bev         = (const float*)d_in[2];
    /* d_in[3] spatial_shapes unused */
    const float* pc_range    = (const float*)d_in[4];
    const float* W_q   = (const float*)d_in[5];
    const float* b_q   = (const float*)d_in[6];
    const float* W_val = (const float*)d_in[7];
    const float* b_val = (const float*)d_in[8];
    const float* W_off = (const float*)d_in[9];
    const float* b_off = (const float*)d_in[10];
    const float* W_attn = (const float*)d_in[11];
    const float* b_attn = (const float*)d_in[12];
    const float* W_do  = (const float*)d_in[13];
    const float* b_do  = (const float*)d_in[14];
    const float* W_out = (const float*)d_in[15];
    const float* b_out = (const float*)d_in[16];
    float* out = (float*)d_out;

    float *pqoa, *pWaug, *pbaug, *pg, *pws, *pbT, *ps, *pm;
    cudaGetSymbolAddress((void**)&pqoa,  g_qoa);
    cudaGetSymbolAddress((void**)&pWaug, g_Waug);
    cudaGetSymbolAddress((void**)&pbaug, g_baug);
    cudaGetSymbolAddress((void**)&pg,    g_gath);
    cudaGetSymbolAddress((void**)&pws,   g_wsum);
    cudaGetSymbolAddress((void**)&pbT,   g_bevT);
    cudaGetSymbolAddress((void**)&ps,    g_samp);
    cudaGetSymbolAddress((void**)&pm,    g_msda);

    // One-time stream/event creation (resource setup only; captured work is
    // identical on every call).
    static cudaStream_t s1 = nullptr;
    static cudaEvent_t evFork = nullptr, evJoin = nullptr;
    if (s1 == nullptr) {
        cudaStreamCreateWithFlags(&s1, cudaStreamNonBlocking);
        cudaEventCreateWithFlags(&evFork, cudaEventDisableTiming);
        cudaEventCreateWithFlags(&evJoin, cudaEventDisableTiming);
    }

    // Fork: transpose (DRAM-bound) runs concurrently with prep + aug GEMM.
    cudaEventRecord(evFork, 0);
    cudaStreamWaitEvent(s1, evFork, 0);

    transpose_kernel<<<dim3(NHW / 64, DIM / 32, NB), 256, 0, s1>>>(bev, pbT);

    prep_weights<<<(DIM * NAUG) / 256, 256>>>(W_q, W_off, W_attn, pWaug);
    prep_bias<<<1, NAUG>>>(b_q, b_off, b_attn, W_off, W_attn, pbaug);
    gemm_v2<<<dim3(NAUG / 64, NROWS / 128), 256>>>(
        query_embed, pWaug, pbaug, nullptr, 0, pqoa, NAUG, NAUG);

    // Join
    cudaEventRecord(evJoin, s1);
    cudaStreamWaitEvent(0, evJoin, 0);

    // gather raw features (corners + softmax inline)
    gather_kernel<<<NROWS, 256>>>(ctrl, pc_range, pbT, pqoa, pg, pws);

    // per-head projection
    proj_kernel<<<dim3(NROWS / 128, NHEADS), 256>>>(pg, pws, W_val, b_val, ps);

    // msda = samp @ W_do + b_do + query
    gemm_v2<<<dim3(DIM / 64, NROWS / 128), 256>>>(
        ps, W_do, b_do, pqoa, NAUG, pm, DIM, DIM);

    // out = msda @ W_out + b_out
    gemm_v2<<<dim3(DIM / 64, NROWS / 128), 256>>>(
        pm, W_out, b_out, nullptr, 0, out, DIM, DIM);
}

// round 6
// speedup vs baseline: 1.4512x; 1.1631x over previous
#include <cuda_runtime.h>
#include <math.h>

#define NB     4
#define NQ     1024
#define DIM    256
#define NHEADS 8
#define GH     200
#define GW     200
#define NHW    (GH*GW)       // 40000
#define NROWS  (NB*NQ)       // 4096
#define NAUG   128           // 64 off | 32 attn logits | 32 pad

// Scratch (__device__ globals: allocation-free per harness rules)
__device__ float g_qoa  [NROWS * NAUG];
__device__ float g_Waug [DIM * NAUG];
__device__ float g_baug [NAUG];
__device__ float g_Wfold[512 * DIM];                     // [W_do@W_out ; W_q@W_out]
__device__ float g_bfold[DIM];
__device__ float g_gath [(size_t)NROWS * NHEADS * DIM];  // 32 MB
__device__ float g_wsum [NROWS * NHEADS];
__device__ float g_bevT [(size_t)NB * NHW * DIM];        // 164 MB
__device__ float g_samp [NROWS * DIM];

// ---------------------------------------------------------------------------
// W_aug = [ W_q@W_off | W_q@W_attn | 0 ]  (128 cols)
// ---------------------------------------------------------------------------
__global__ __launch_bounds__(256)
void prep_weights(const float* __restrict__ W_q, const float* __restrict__ W_off,
                  const float* __restrict__ W_attn, float* __restrict__ W_aug)
{
    const int id = blockIdx.x * 256 + threadIdx.x;   // 256*128
    const int k = id >> 7, n = id & 127;
    float v = 0.f;
    if (n < 64) {
        float s = 0.f;
        for (int i = 0; i < 256; i++) s = fmaf(W_q[k * 256 + i], W_off[i * 64 + n], s);
        v = s;
    } else if (n < 96) {
        const int j = n - 64;
        float s = 0.f;
        for (int i = 0; i < 256; i++) s = fmaf(W_q[k * 256 + i], W_attn[i * 32 + j], s);
        v = s;
    }
    W_aug[id] = v;
}

__global__ void prep_bias(const float* __restrict__ b_q, const float* __restrict__ b_off,
                          const float* __restrict__ b_attn,
                          const float* __restrict__ W_off, const float* __restrict__ W_attn,
                          float* __restrict__ b_aug)
{
    const int n = threadIdx.x;   // 128
    float v = 0.f;
    if (n < 64) {
        float s = b_off[n];
        for (int i = 0; i < 256; i++) s = fmaf(b_q[i], W_off[i * 64 + n], s);
        v = s;
    } else if (n < 96) {
        const int j = n - 64;
        float s = b_attn[j];
        for (int i = 0; i < 256; i++) s = fmaf(b_q[i], W_attn[i * 32 + j], s);
        v = s;
    }
    b_aug[n] = v;
}

// b_fold = (b_do + b_q) @ W_out + b_out
__global__ void prep_bfold(const float* __restrict__ b_q, const float* __restrict__ b_do,
                           const float* __restrict__ b_out, const float* __restrict__ W_out,
                           float* __restrict__ bf)
{
    const int n = threadIdx.x;   // 256
    float s = b_out[n];
    for (int k = 0; k < 256; k++) s = fmaf(b_do[k] + b_q[k], W_out[k * 256 + n], s);
    bf[n] = s;
}

// ---------------------------------------------------------------------------
// GEMM: C[M x N] = A[M x 256] @ W[256 x N] + bias (+ res)
// BM=128, BN=64, BK=16, 256 threads, 8x4 microtile. M mult of 128.
// ---------------------------------------------------------------------------
__global__ __launch_bounds__(256)
void gemm_v2(const float* __restrict__ A, const float* __restrict__ W,
             const float* __restrict__ bias, const float* __restrict__ res, int ldres,
             float* __restrict__ C, int ldc, int ldw)
{
    __shared__ float As[16][132];
    __shared__ __align__(16) float Bs[16][64];

    const int tid = threadIdx.x;
    const int tx = tid & 15, ty = tid >> 4;
    const int n0 = blockIdx.x * 64;
    const int m0 = blockIdx.y * 128;

    float acc[8][4];
#pragma unroll
    for (int i = 0; i < 8; i++)
#pragma unroll
        for (int j = 0; j < 4; j++) acc[i][j] = 0.f;

    for (int k0 = 0; k0 < 256; k0 += 16) {
        {
            const int mr = tid >> 2;
            const int kq = (tid & 3) * 4;
#pragma unroll
            for (int r = 0; r < 2; r++) {
                const int m = mr + 64 * r;
                float4 v = *(const float4*)(A + (size_t)(m0 + m) * 256 + k0 + kq);
                As[kq + 0][m] = v.x; As[kq + 1][m] = v.y;
                As[kq + 2][m] = v.z; As[kq + 3][m] = v.w;
            }
        }
        {
            const int kr = tid >> 4;
            const int nq = (tid & 15) * 4;
            *(float4*)&Bs[kr][nq] = *(const float4*)(W + (size_t)(k0 + kr) * ldw + n0 + nq);
        }
        __syncthreads();

#pragma unroll
        for (int k = 0; k < 16; k++) {
            float a[8], b[4];
#pragma unroll
            for (int i = 0; i < 4; i++) {
                a[i]     = As[k][ty * 4 + i];
                a[i + 4] = As[k][64 + ty * 4 + i];
            }
#pragma unroll
            for (int j = 0; j < 4; j++) b[j] = Bs[k][tx * 4 + j];
#pragma unroll
            for (int i = 0; i < 8; i++)
#pragma unroll
                for (int j = 0; j < 4; j++)
                    acc[i][j] = fmaf(a[i], b[j], acc[i][j]);
        }
        __syncthreads();
    }

#pragma unroll
    for (int i = 0; i < 8; i++) {
        const int m = m0 + (i < 4 ? ty * 4 + i : 64 + ty * 4 + (i - 4));
#pragma unroll
        for (int j = 0; j < 4; j++) {
            const int n = n0 + tx * 4 + j;
            float v = acc[i][j] + (bias ? bias[n] : 0.f);
            if (res) v += res[(size_t)m * ldres + n];
            C[(size_t)m * ldc + n] = v;
        }
    }
}

// ---------------------------------------------------------------------------
// Dual-A GEMM (K=512): C = [A1 | A2] @ W512 + bias.  N=256.
// ---------------------------------------------------------------------------
__global__ __launch_bounds__(256)
void gemm_dual(const float* __restrict__ A1, const float* __restrict__ A2,
               const float* __restrict__ W, const float* __restrict__ bias,
               float* __restrict__ C)
{
    __shared__ float As[16][132];
    __shared__ __align__(16) float Bs[16][64];

    const int tid = threadIdx.x;
    const int tx = tid & 15, ty = tid >> 4;
    const int n0 = blockIdx.x * 64;
    const int m0 = blockIdx.y * 128;

    float acc[8][4];
#pragma unroll
    for (int i = 0; i < 8; i++)
#pragma unroll
        for (int j = 0; j < 4; j++) acc[i][j] = 0.f;

    for (int k0 = 0; k0 < 512; k0 += 16) {
        const float* A = (k0 < 256) ? A1 : A2;
        const int kk = (k0 < 256) ? k0 : k0 - 256;
        {
            const int mr = tid >> 2;
            const int kq = (tid & 3) * 4;
#pragma unroll
            for (int r = 0; r < 2; r++) {
                const int m = mr + 64 * r;
                float4 v = *(const float4*)(A + (size_t)(m0 + m) * 256 + kk + kq);
                As[kq + 0][m] = v.x; As[kq + 1][m] = v.y;
                As[kq + 2][m] = v.z; As[kq + 3][m] = v.w;
            }
        }
        {
            const int kr = tid >> 4;
            const int nq = (tid & 15) * 4;
            *(float4*)&Bs[kr][nq] = *(const float4*)(W + (size_t)(k0 + kr) * 256 + n0 + nq);
        }
        __syncthreads();

#pragma unroll
        for (int k = 0; k < 16; k++) {
            float a[8], b[4];
#pragma unroll
            for (int i = 0; i < 4; i++) {
                a[i]     = As[k][ty * 4 + i];
                a[i + 4] = As[k][64 + ty * 4 + i];
            }
#pragma unroll
            for (int j = 0; j < 4; j++) b[j] = Bs[k][tx * 4 + j];
#pragma unroll
            for (int i = 0; i < 8; i++)
#pragma unroll
                for (int j = 0; j < 4; j++)
                    acc[i][j] = fmaf(a[i], b[j], acc[i][j]);
        }
        __syncthreads();
    }

#pragma unroll
    for (int i = 0; i < 8; i++) {
        const int m = m0 + (i < 4 ? ty * 4 + i : 64 + ty * 4 + (i - 4));
#pragma unroll
        for (int j = 0; j < 4; j++) {
            const int n = n0 + tx * 4 + j;
            C[(size_t)m * 256 + n] = acc[i][j] + bias[n];
        }
    }
}

// ---------------------------------------------------------------------------
// Transpose bev [B, C=256, HW] -> bevT [B, HW, C]. 32(C) x 64(HW) tiles, float4.
// ---------------------------------------------------------------------------
__global__ __launch_bounds__(256)
void transpose_kernel(const float* __restrict__ src, float* __restrict__ dst)
{
    __shared__ float tile[32 * 65];
    const int b  = blockIdx.z;
    const int p0 = blockIdx.x * 64;
    const int c0 = blockIdx.y * 32;
    const int tid = threadIdx.x;

#pragma unroll
    for (int l = 0; l < 2; l++) {
        const int c = l * 16 + (tid >> 4);
        const int p = (tid & 15) * 4;
        float4 v = *(const float4*)(src + ((size_t)(b * 256 + c0 + c)) * NHW + p0 + p);
        tile[c * 65 + p + 0] = v.x;
        tile[c * 65 + p + 1] = v.y;
        tile[c * 65 + p + 2] = v.z;
        tile[c * 65 + p + 3] = v.w;
    }
    __syncthreads();

#pragma unroll
    for (int l = 0; l < 2; l++) {
        const int p  = l * 32 + (tid >> 3);
        const int cq = (tid & 7) * 4;
        float4 v;
        v.x = tile[(cq + 0) * 65 + p];
        v.y = tile[(cq + 1) * 65 + p];
        v.z = tile[(cq + 2) * 65 + p];
        v.w = tile[(cq + 3) * 65 + p];
        *(float4*)(dst + ((size_t)b * NHW + p0 + p) * 256 + c0 + cq) = v;
    }
}

// ---------------------------------------------------------------------------
// Gather with pixel dedup. Block per row.
//  P1 (t<32): Bezier + softmax + corners -> 128 (pixel, head, weight) entries
//  P2: hash-dedup into (unique pixel, per-head weight[8]) table
//  P3: compact slots
//  P4: each unique pixel's 1KB feature loaded once; FMA into all 8 heads
//  P5: reduce 4 stripes, write g[row][h][256]
// ---------------------------------------------------------------------------
__global__ __launch_bounds__(256)
void gather_kernel(const float* __restrict__ ctrl, const float* __restrict__ pcr,
                   const float* __restrict__ bevT, const float* __restrict__ qoa,
                   float* __restrict__ g, float* __restrict__ wsum)
{
    const int row = blockIdx.x;
    const int b = row >> 10;
    const int t = threadIdx.x;

    __shared__ int    s_idx[128];
    __shared__ float  s_w[128];
    __shared__ float  ws[32];
    __shared__ int    hidx[256];
    __shared__ float  hw[256][8];
    __shared__ int    slots[128];
    __shared__ int    cnt;
    __shared__ float4 red4[4 * 8 * 64];   // 32KB

    // init hash
    hidx[t] = -1;
    {
        float* hwf = &hw[0][0];
#pragma unroll
        for (int i = 0; i < 8; i++) hwf[t + 256 * i] = 0.f;
    }
    if (t == 0) cnt = 0;

    if (t < 32) {
        const float lox = pcr[0], loy = pcr[1];
        const float spx = pcr[3] - pcr[0], spy = pcr[4] - pcr[1];
        const float* cp = ctrl + (size_t)row * 8;
        const float c0x = cp[0], c0y = cp[1], c1x = cp[2], c1y = cp[3];
        const float c2x = cp[4], c2y = cp[5], c3x = cp[6], c3y = cp[7];
        float sx = 0.f, sy = 0.f;
#pragma unroll
        for (int k = 0; k < 10; k++) {
            const float tt = (float)k / 9.0f;
            const float u = 1.0f - tt;
            const float w0 = u*u*u, w1 = 3.f*u*u*tt, w2 = 3.f*u*tt*tt, w3 = tt*tt*tt;
            const float dx = w0*c0x + w1*c1x + w2*c2x + w3*c3x;
            const float dy = w0*c0y + w1*c1y + w2*c2y + w3*c3y;
            sx += fminf(fmaxf((dx - lox) / spx, 0.01f), 0.99f);
            sy += fminf(fmaxf((dy - loy) / spy, 0.01f), 0.99f);
        }
        const float rcx = sx * 0.1f, rcy = sy * 0.1f;

        const int h = t >> 2, p = t & 3;
        const float* lg = qoa + (size_t)row * NAUG + 64 + h * 4;
        const float l0 = lg[0], l1 = lg[1], l2 = lg[2], l3 = lg[3];
        const float m = fmaxf(fmaxf(l0, l1), fmaxf(l2, l3));
        const float e0 = expf(l0 - m), e1 = expf(l1 - m), e2 = expf(l2 - m), e3 = expf(l3 - m);
        const float lp = (p == 0) ? l0 : (p == 1) ? l1 : (p == 2) ? l2 : l3;
        const float aw = expf(lp - m) / (e0 + e1 + e2 + e3);

        const float ox = qoa[(size_t)row * NAUG + h * 8 + p * 2 + 0];
        const float oy = qoa[(size_t)row * NAUG + h * 8 + p * 2 + 1];
        const float x = (rcx + ox / (float)GW) * (float)GW - 0.5f;
        const float y = (rcy + oy / (float)GH) * (float)GH - 0.5f;
        const float fx = floorf(x), fy = floorf(y);
        const int x0 = (int)fx, y0 = (int)fy;
        const int x1 = x0 + 1,  y1 = y0 + 1;
        const float wx = x - fx, wy = y - fy;
        const bool vx0 = (x0 >= 0) & (x0 < GW), vx1 = (x1 >= 0) & (x1 < GW);
        const bool vy0 = (y0 >= 0) & (y0 < GH), vy1 = (y1 >= 0) & (y1 < GH);
        const int cx0 = min(max(x0, 0), GW - 1), cx1 = min(max(x1, 0), GW - 1);
        const int cy0 = min(max(y0, 0), GH - 1), cy1 = min(max(y1, 0), GH - 1);
        const float w00 = (vy0 & vx0) ? (1.f - wx) * (1.f - wy) * aw : 0.f;
        const float w01 = (vy0 & vx1) ? wx * (1.f - wy) * aw : 0.f;
        const float w10 = (vy1 & vx0) ? (1.f - wx) * wy * aw : 0.f;
        const float w11 = (vy1 & vx1) ? wx * wy * aw : 0.f;
        s_idx[t*4+0] = cy0 * GW + cx0;  s_w[t*4+0] = w00;
        s_idx[t*4+1] = cy0 * GW + cx1;  s_w[t*4+1] = w01;
        s_idx[t*4+2] = cy1 * GW + cx0;  s_w[t*4+2] = w10;
        s_idx[t*4+3] = cy1 * GW + cx1;  s_w[t*4+3] = w11;
        ws[t] = w00 + w01 + w10 + w11;
    }
    __syncthreads();

    // P2: dedup insert (threads 0..127, one corner entry each)
    if (t < 128) {
        const int idx = s_idx[t];
        const float w = s_w[t];
        const int h = t >> 4;                 // (h = hp>>2 where hp = t>>2) -> t>>4
        unsigned s = ((unsigned)idx * 2654435761u) >> 24;
        while (true) {
            int prev = atomicCAS(&hidx[s], -1, idx);
            if (prev == -1 || prev == idx) { atomicAdd(&hw[s][h], w); break; }
            s = (s + 1) & 255;
        }
    }
    __syncthreads();

    // P3: compact occupied slots
    if (hidx[t] >= 0) {
        const int p = atomicAdd(&cnt, 1);
        slots[p] = t;
    }
    __syncthreads();

    // P4: gather unique pixels, FMA into 8 heads
    const int cq = t & 63;        // channel quad
    const int stripe = t >> 6;    // 0..3
    float4 acc8[8];
#pragma unroll
    for (int h = 0; h < 8; h++) acc8[h] = make_float4(0.f, 0.f, 0.f, 0.f);

    const int n = cnt;
    const float* basep = bevT + ((size_t)b * NHW) * 256 + cq * 4;
    for (int i = stripe; i < n; i += 4) {
        const int slot = slots[i];
        const int pix = hidx[slot];
        const float4 v = *(const float4*)(basep + (size_t)pix * 256);
#pragma unroll
        for (int h = 0; h < 8; h++) {
            const float w = hw[slot][h];
            acc8[h].x = fmaf(w, v.x, acc8[h].x);
            acc8[h].y = fmaf(w, v.y, acc8[h].y);
            acc8[h].z = fmaf(w, v.z, acc8[h].z);
            acc8[h].w = fmaf(w, v.w, acc8[h].w);
        }
    }
#pragma unroll
    for (int h = 0; h < 8; h++)
        red4[(stripe * 8 + h) * 64 + cq] = acc8[h];
    __syncthreads();

    // P5: reduce stripes, write g
#pragma unroll
    for (int j = 0; j < 2; j++) {
        const int pos = t + j * 256;          // 0..511
        const int h = pos >> 6, q = pos & 63;
        float4 a = red4[(0 * 8 + h) * 64 + q];
        const float4 b1 = red4[(1 * 8 + h) * 64 + q];
        const float4 b2 = red4[(2 * 8 + h) * 64 + q];
        const float4 b3 = red4[(3 * 8 + h) * 64 + q];
        a.x += b1.x + b2.x + b3.x;
        a.y += b1.y + b2.y + b3.y;
        a.z += b1.z + b2.z + b3.z;
        a.w += b1.w + b2.w + b3.w;
        *(float4*)(g + ((size_t)row * 8 + h) * 256 + q * 4) = a;
    }

    if (t < 8)
        wsum[(size_t)row * 8 + t] = ws[t*4] + ws[t*4+1] + ws[t*4+2] + ws[t*4+3];
}

// ---------------------------------------------------------------------------
// Block-diagonal projection: samp[row][h*32+d] = g[row*8+h] . W_val[:,h*32+d]
//                                              + wsum[row,h]*b_val[h*32+d]
// ---------------------------------------------------------------------------
__global__ __launch_bounds__(256)
void proj_kernel(const float* __restrict__ g, const float* __restrict__ wsum,
                 const float* __restrict__ W_val, const float* __restrict__ b_val,
                 float* __restrict__ samp)
{
    const int h  = blockIdx.y;
    const int r0 = blockIdx.x * 128;
    const int t  = threadIdx.x;
    const int d = t & 31, rg = t >> 5;

    __shared__ float Ws[256 * 32];
    __shared__ float As[128 * 36];

#pragma unroll
    for (int i = 0; i < 32; i++) {
        const int k = i * 8 + (t >> 5);
        Ws[k * 32 + d] = W_val[(size_t)k * 256 + h * 32 + d];
    }
    const float bv = b_val[h * 32 + d];

    float acc[16];
#pragma unroll
    for (int r = 0; r < 16; r++) acc[r] = 0.f;

    for (int kt = 0; kt < 8; kt++) {
        __syncthreads();
        {
            const int i = t >> 1, half = t & 1;
            const float* src = g + ((size_t)(r0 + i) * 8 + h) * 256 + kt * 32 + half * 16;
            float* dst = &As[i * 36 + half * 16];
#pragma unroll
            for (int q = 0; q < 4; q++)
                *(float4*)(dst + q * 4) = *(const float4*)(src + q * 4);
        }
        __syncthreads();

#pragma unroll
        for (int k = 0; k < 32; k++) {
            const float wv = Ws[(kt * 32 + k) * 32 + d];
#pragma unroll
            for (int r = 0; r < 16; r++)
                acc[r] = fmaf(As[(rg * 16 + r) * 36 + k], wv, acc[r]);
        }
    }

#pragma unroll
    for (int r = 0; r < 16; r++) {
        const int row = r0 + rg * 16 + r;
        samp[(size_t)row * 256 + h * 32 + d] = acc[r] + wsum[(size_t)row * 8 + h] * bv;
    }
}

// ---------------------------------------------------------------------------
extern "C" void kernel_launch(void* const* d_in, const int* in_sizes, int n_in,
                              void* d_out, int out_size)
{
    const float* query_embed = (const float*)d_in[0];
    const float* ctrl        = (const float*)d_in[1];
    const float* bev         = (const float*)d_in[2];
    /* d_in[3] spatial_shapes unused */
    const float* pc_range    = (const float*)d_in[4];
    const float* W_q   = (const float*)d_in[5];
    const float* b_q   = (const float*)d_in[6];
    const float* W_val = (const float*)d_in[7];
    const float* b_val = (const float*)d_in[8];
    const float* W_off = (const float*)d_in[9];
    const float* b_off = (const float*)d_in[10];
    const float* W_attn = (const float*)d_in[11];
    const float* b_attn = (const float*)d_in[12];
    const float* W_do  = (const float*)d_in[13];
    const float* b_do  = (const float*)d_in[14];
    const float* W_out = (const float*)d_in[15];
    const float* b_out = (const float*)d_in[16];
    float* out = (float*)d_out;

    float *pqoa, *pWaug, *pbaug, *pWfold, *pbfold, *pg, *pws, *pbT, *ps;
    cudaGetSymbolAddress((void**)&pqoa,  g_qoa);
    cudaGetSymbolAddress((void**)&pWaug, g_Waug);
    cudaGetSymbolAddress((void**)&pbaug, g_baug);
    cudaGetSymbolAddress((void**)&pWfold, g_Wfold);
    cudaGetSymbolAddress((void**)&pbfold, g_bfold);
    cudaGetSymbolAddress((void**)&pg,    g_gath);
    cudaGetSymbolAddress((void**)&pws,   g_wsum);
    cudaGetSymbolAddress((void**)&pbT,   g_bevT);
    cudaGetSymbolAddress((void**)&ps,    g_samp);

    static cudaStream_t s1 = nullptr, s2 = nullptr;
    static cudaEvent_t evFork = nullptr, evT = nullptr, evS2 = nullptr;
    if (s1 == nullptr) {
        cudaStreamCreateWithFlags(&s1, cudaStreamNonBlocking);
        cudaStreamCreateWithFlags(&s2, cudaStreamNonBlocking);
        cudaEventCreateWithFlags(&evFork, cudaEventDisableTiming);
        cudaEventCreateWithFlags(&evT,    cudaEventDisableTiming);
        cudaEventCreateWithFlags(&evS2,   cudaEventDisableTiming);
    }

    cudaEventRecord(evFork, 0);
    cudaStreamWaitEvent(s1, evFork, 0);
    cudaStreamWaitEvent(s2, evFork, 0);

    // s1: DRAM-bound transpose
    transpose_kernel<<<dim3(NHW / 64, DIM / 32, NB), 256, 0, s1>>>(bev, pbT);
    cudaEventRecord(evT, s1);

    // s2: weight folds for the fused output GEMM (concurrent with transpose)
    prep_bfold<<<1, 256, 0, s2>>>(b_q, b_do, b_out, W_out, pbfold);
    gemm_v2<<<dim3(4, 2), 256, 0, s2>>>(W_do, W_out, nullptr, nullptr, 0,
                                        pWfold, 256, 256);
    gemm_v2<<<dim3(4, 2), 256, 0, s2>>>(W_q, W_out, nullptr, nullptr, 0,
                                        pWfold + 256 * 256, 256, 256);
    cudaEventRecord(evS2, s2);

    // main: offsets/logits path
    prep_weights<<<(DIM * NAUG) / 256, 256>>>(W_q, W_off, W_attn, pWaug);
    prep_bias<<<1, NAUG>>>(b_q, b_off, b_attn, W_off, W_attn, pbaug);
    gemm_v2<<<dim3(NAUG / 64, NROWS / 128), 256>>>(
        query_embed, pWaug, pbaug, nullptr, 0, pqoa, NAUG, NAUG);

    cudaStreamWaitEvent(0, evT, 0);

    // gather (dedup) + per-head projection
    gather_kernel<<<NROWS, 256>>>(ctrl, pc_range, pbT, pqoa, pg, pws);
    proj_kernel<<<dim3(NROWS / 128, NHEADS), 256>>>(pg, pws, W_val, b_val, ps);

    cudaStreamWaitEvent(0, evS2, 0);

    // out = samp@(W_do W_out) + qe@(W_q W_out) + b_fold
    gemm_dual<<<dim3(DIM / 64, NROWS / 128), 256>>>(
        ps, query_embed, pWfold, pbfold, out);
}